// round 5
// baseline (speedup 1.0000x reference)
#include <cuda_runtime.h>
#include <cuda_bf16.h>
#include <math.h>

#define BB 128
#define TT 256
#define HH 768
#define KK 64

typedef unsigned long long u64t;

__device__ float g_emis[BB * TT * KK];   // emissions scratch, 8 MB

// ---- packed f32x2 helpers ------------------------------------------------
__device__ __forceinline__ u64t ffma2(u64t a, u64t b, u64t c) {
    u64t d;
    asm("fma.rn.f32x2 %0, %1, %2, %3;" : "=l"(d) : "l"(a), "l"(b), "l"(c));
    return d;
}
__device__ __forceinline__ u64t pack2(float lo, float hi) {
    u64t d;
    unsigned a = __float_as_uint(lo), b = __float_as_uint(hi);
    asm("mov.b64 %0, {%1, %2};" : "=l"(d) : "r"(a), "r"(b));
    return d;
}
__device__ __forceinline__ void unpack2(u64t v, float* lo, float* hi) {
    unsigned a, b;
    asm("mov.b64 {%0, %1}, %2;" : "=r"(a), "=r"(b) : "l"(v));
    *lo = __uint_as_float(a);
    *hi = __uint_as_float(b);
}

// ---------------------------------------------------------------------------
// Kernel 1: emissions = hidden @ W + b (unchanged; ~90% of FFMA2 pacing floor)
// ---------------------------------------------------------------------------
__global__ __launch_bounds__(256) void gemm_emis_kernel(
    const float* __restrict__ A,
    const float* __restrict__ Wm,
    const float* __restrict__ bias)
{
    __shared__ float As[16][132];
    __shared__ float Bs[16][64];

    const int tid = threadIdx.x;
    const int m0 = blockIdx.x * 128;
    const int ty = tid >> 4;
    const int tx = tid & 15;

    u64t acc2[4][4];
#pragma unroll
    for (int rp = 0; rp < 4; rp++)
#pragma unroll
        for (int c = 0; c < 4; c++) acc2[rp][c] = 0ull;

    const int arow0 = (tid) >> 2,       ac40 = (tid) & 3;
    const int arow1 = (tid + 256) >> 2, ac41 = (tid + 256) & 3;
    const int brow = tid >> 4, bc4 = tid & 15;

    float4 aReg0 = *(const float4*)&A[(size_t)(m0 + arow0) * HH + ac40 * 4];
    float4 aReg1 = *(const float4*)&A[(size_t)(m0 + arow1) * HH + ac41 * 4];
    float4 bReg  = *(const float4*)&Wm[(size_t)(brow) * KK + bc4 * 4];

    for (int kt = 0; kt < HH; kt += 16) {
        As[ac40 * 4 + 0][arow0] = aReg0.x;
        As[ac40 * 4 + 1][arow0] = aReg0.y;
        As[ac40 * 4 + 2][arow0] = aReg0.z;
        As[ac40 * 4 + 3][arow0] = aReg0.w;
        As[ac41 * 4 + 0][arow1] = aReg1.x;
        As[ac41 * 4 + 1][arow1] = aReg1.y;
        As[ac41 * 4 + 2][arow1] = aReg1.z;
        As[ac41 * 4 + 3][arow1] = aReg1.w;
        *(float4*)&Bs[brow][bc4 * 4] = bReg;
        __syncthreads();

        if (kt + 16 < HH) {
            aReg0 = *(const float4*)&A[(size_t)(m0 + arow0) * HH + kt + 16 + ac40 * 4];
            aReg1 = *(const float4*)&A[(size_t)(m0 + arow1) * HH + kt + 16 + ac41 * 4];
            bReg  = *(const float4*)&Wm[(size_t)(kt + 16 + brow) * KK + bc4 * 4];
        }

#pragma unroll
        for (int kk = 0; kk < 16; kk++) {
            const u64t* ap = (const u64t*)&As[kk][ty * 8];
            u64t a2[4];
#pragma unroll
            for (int rp = 0; rp < 4; rp++) a2[rp] = ap[rp];
            float4 bv = *(const float4*)&Bs[kk][tx * 4];
            u64t bd[4];
            bd[0] = pack2(bv.x, bv.x);
            bd[1] = pack2(bv.y, bv.y);
            bd[2] = pack2(bv.z, bv.z);
            bd[3] = pack2(bv.w, bv.w);
#pragma unroll
            for (int rp = 0; rp < 4; rp++)
#pragma unroll
                for (int c = 0; c < 4; c++)
                    acc2[rp][c] = ffma2(a2[rp], bd[c], acc2[rp][c]);
        }
        __syncthreads();
    }

    float4 bb = *(const float4*)&bias[tx * 4];
    const float bbv[4] = {bb.x, bb.y, bb.z, bb.w};
#pragma unroll
    for (int rp = 0; rp < 4; rp++) {
        float o0[4], o1[4];
#pragma unroll
        for (int c = 0; c < 4; c++) {
            float lo, hi;
            unpack2(acc2[rp][c], &lo, &hi);
            o0[c] = lo + bbv[c];
            o1[c] = hi + bbv[c];
        }
        int row = m0 + ty * 8 + 2 * rp;
        *(float4*)&g_emis[(size_t)row * KK + tx * 4]       = make_float4(o0[0], o0[1], o0[2], o0[3]);
        *(float4*)&g_emis[(size_t)(row + 1) * KK + tx * 4] = make_float4(o1[0], o1[1], o1[2], o1[3]);
    }
}

// ---------------------------------------------------------------------------
// Kernel 2: CRF. grid=128 (ONE wave), block=320 threads:
//   warps 0..7  (tid 0..255):   Viterbi, 4 threads/state, bar.sync 1,256
//   warps 8..9  (tid 256..319): forward log-norm + seq_score, bar.sync 2,64
// The two roles never synchronize with each other -> independent pacing.
// ---------------------------------------------------------------------------
__global__ __launch_bounds__(320) void crf_kernel(
    const int* __restrict__ masks,
    const int* __restrict__ target,
    const float* __restrict__ trans_g,
    float* __restrict__ out_dec,
    float* __restrict__ out_ll)
{
    __shared__ __align__(16) float s_v[2][64];     // viterbi values
    __shared__ __align__(16) float s_P[2][64];     // forward probs
    __shared__ float s_red[4];
    __shared__ int s_len_v, s_len_f;
    __shared__ int s_path[TT];
    __shared__ unsigned char s_bp[(TT - 1) * KK];

    const int tid = threadIdx.x;
    const int b = blockIdx.x;
    const float* emisb = &g_emis[(size_t)b * TT * KK];

    if (tid < 256) {
        // ================= VITERBI: 8 warps, 4 threads per state ============
        if (tid < 32) {
            int acc = 0;
#pragma unroll
            for (int i = 0; i < 8; i++) acc += masks[b * TT + tid + 32 * i];
#pragma unroll
            for (int o = 16; o; o >>= 1) acc += __shfl_xor_sync(0xFFFFFFFFu, acc, o);
            if (tid == 0) s_len_v = acc;
        }

        const int j = tid >> 2;      // state 0..63
        const int q = tid & 3;       // quarter 0..3
        const int k0 = q * 16;

        float Tcol[16];
#pragma unroll
        for (int kk = 0; kk < 16; kk++)
            Tcol[kk] = trans_g[(k0 + kk) * KK + j];

        float e0 = emisb[j];
        float eA = emisb[KK + j];
        float eB = emisb[2 * KK + j];
        float prevV = e0;
        if (q == 0) s_v[0][j] = e0;
        asm volatile("bar.sync 1, 256;" ::: "memory");
        const int len = s_len_v;
        int buf = 0;

        for (int t = 1; t < TT; t++) {
            float eC = (t + 2 < TT) ? emisb[(size_t)(t + 2) * KK + j] : 0.f;

            const float4* V4 = (const float4*)&s_v[buf][k0];
            float4 v0 = V4[0], v1 = V4[1], v2 = V4[2], v3 = V4[3];
            float a[16];
            a[0]  = v0.x + Tcol[0];  a[1]  = v0.y + Tcol[1];
            a[2]  = v0.z + Tcol[2];  a[3]  = v0.w + Tcol[3];
            a[4]  = v1.x + Tcol[4];  a[5]  = v1.y + Tcol[5];
            a[6]  = v1.z + Tcol[6];  a[7]  = v1.w + Tcol[7];
            a[8]  = v2.x + Tcol[8];  a[9]  = v2.y + Tcol[9];
            a[10] = v2.z + Tcol[10]; a[11] = v2.w + Tcol[11];
            a[12] = v3.x + Tcol[12]; a[13] = v3.y + Tcol[13];
            a[14] = v3.z + Tcol[14]; a[15] = v3.w + Tcol[15];

            float pv[8];
            int pi[8];
#pragma unroll
            for (int m = 0; m < 8; m++) {
                bool g = a[2 * m + 1] > a[2 * m];      // strict: lower k wins ties
                pv[m] = g ? a[2 * m + 1] : a[2 * m];
                pi[m] = k0 + 2 * m + (g ? 1 : 0);
            }
#pragma unroll
            for (int s = 1; s < 8; s <<= 1) {
#pragma unroll
                for (int m = 0; m < 8; m += 2 * s) {
                    bool g = pv[m + s] > pv[m];
                    pv[m] = g ? pv[m + s] : pv[m];
                    pi[m] = g ? pi[m + s] : pi[m];
                }
            }
            float bv = pv[0];
            int   ba = pi[0];

            // tie-aware cross-thread combine (exact first-max semantics)
            float ov = __shfl_xor_sync(0xFFFFFFFFu, bv, 1);
            int   oa = __shfl_xor_sync(0xFFFFFFFFu, ba, 1);
            if (ov > bv || (ov == bv && oa < ba)) { bv = ov; ba = oa; }
            ov = __shfl_xor_sync(0xFFFFFFFFu, bv, 2);
            oa = __shfl_xor_sync(0xFFFFFFFFu, ba, 2);
            if (ov > bv || (ov == bv && oa < ba)) { bv = ov; ba = oa; }

            if (q == 0) {
                int bp;
                if (t < len) { prevV = bv + eA; bp = ba; }
                else         { bp = j; }
                s_v[buf ^ 1][j] = prevV;
                s_bp[(t - 1) * KK + j] = (unsigned char)bp;
            }
            eA = eB;
            eB = eC;
            asm volatile("bar.sync 1, 256;" ::: "memory");
            buf ^= 1;
        }

        if (tid == 0) {
            float bvv = s_v[buf][0];
            int tg = 0;
#pragma unroll
            for (int k = 1; k < KK; k++)
                if (s_v[buf][k] > bvv) { bvv = s_v[buf][k]; tg = k; }
            s_path[TT - 1] = tg;
            for (int t = TT - 1; t >= 1; t--) {
                tg = s_bp[(t - 1) * KK + tg];
                s_path[t - 1] = tg;
            }
        }
        asm volatile("bar.sync 1, 256;" ::: "memory");
        out_dec[(size_t)b * TT + tid] = (float)((tid < len) ? s_path[tid] : 0);

    } else {
        // ================= FORWARD: 2 warps (tid 256..319) =================
        const int ft = tid - 256;     // 0..63

        if (ft < 32) {
            int acc = 0;
#pragma unroll
            for (int i = 0; i < 8; i++) acc += masks[b * TT + ft + 32 * i];
#pragma unroll
            for (int o = 16; o; o >>= 1) acc += __shfl_xor_sync(0xFFFFFFFFu, acc, o);
            if (ft == 0) s_len_f = acc;
        }

        const int j = ft;
        u64t E2[32];
#pragma unroll
        for (int m = 0; m < 32; m++) {
            float t0 = trans_g[(2 * m) * KK + j];
            float t1 = trans_g[(2 * m + 1) * KK + j];
            E2[m] = pack2(expf(t0), expf(t1));
        }

        float e0 = emisb[j];
        float eA = emisb[KK + j];
        float eB = emisb[2 * KK + j];
        float prevP = __expf(e0);
        int iexp = 0;
        s_P[0][j] = prevP;
        asm volatile("bar.sync 2, 64;" ::: "memory");
        const int len = s_len_f;
        int buf = 0;

        for (int t = 1; t < TT; t++) {
            float eC = (t + 2 < TT) ? emisb[(size_t)(t + 2) * KK + j] : 0.f;

            float p0 = s_P[buf][0];
            const u64t* P2 = (const u64t*)&s_P[buf][0];
            u64t s0 = 0ull, s1 = 0ull, s2 = 0ull, s3 = 0ull;
#pragma unroll
            for (int m = 0; m < 8; m++) {
                s0 = ffma2(P2[4 * m + 0], E2[4 * m + 0], s0);
                s1 = ffma2(P2[4 * m + 1], E2[4 * m + 1], s1);
                s2 = ffma2(P2[4 * m + 2], E2[4 * m + 2], s2);
                s3 = ffma2(P2[4 * m + 3], E2[4 * m + 3], s3);
            }
            float l0, h0, l1, h1, l2, h2, l3, h3;
            unpack2(s0, &l0, &h0);
            unpack2(s1, &l1, &h1);
            unpack2(s2, &l2, &h2);
            unpack2(s3, &l3, &h3);
            float S = ((l0 + h0) + (l1 + h1)) + ((l2 + h2) + (l3 + h3));

            // exact power-of-2 rescale by p0's exponent
            int e0i = (int)(__float_as_uint(p0) >> 23);
            float scale = __uint_as_float((unsigned)(254 - e0i) << 23);
            if (t < len) {
                prevP = S * scale * __expf(eA);
                iexp += e0i - 127;
            }
            s_P[buf ^ 1][j] = prevP;
            eA = eB;
            eB = eC;
            asm volatile("bar.sync 2, 64;" ::: "memory");
            buf ^= 1;
        }

        // log_norm: sum final P across 64 threads
        float sp = prevP;
#pragma unroll
        for (int o = 16; o; o >>= 1) sp += __shfl_xor_sync(0xFFFFFFFFu, sp, o);
        if ((ft & 31) == 0) s_red[ft >> 5] = sp;

        // seq_score partials: 4 t's per thread
        float uacc = 0.f;
#pragma unroll
        for (int i = 0; i < 4; i++) {
            int tt = ft + 64 * i;
            if (tt < len) {
                int tg = target[b * TT + tt];
                uacc += emisb[(size_t)tt * KK + tg];
                if (tt >= 1) uacc += trans_g[target[b * TT + tt - 1] * KK + tg];
            }
        }
#pragma unroll
        for (int o = 16; o; o >>= 1) uacc += __shfl_xor_sync(0xFFFFFFFFu, uacc, o);
        if ((ft & 31) == 0) s_red[2 + (ft >> 5)] = uacc;
        asm volatile("bar.sync 2, 64;" ::: "memory");

        if (ft == 0) {
            float sumP = s_red[0] + s_red[1];
            float score = s_red[2] + s_red[3];
            const float LN2 = 0.69314718055994531f;
            out_ll[b] = score - ((float)iexp * LN2 + logf(sumP));
        }
    }
}

// ---------------------------------------------------------------------------
extern "C" void kernel_launch(void* const* d_in, const int* in_sizes, int n_in,
                              void* d_out, int out_size) {
    const float* hidden = (const float*)d_in[0];
    const int*   masks  = (const int*)d_in[1];
    const int*   target = (const int*)d_in[2];
    const float* Wm     = (const float*)d_in[3];
    const float* bias   = (const float*)d_in[4];
    const float* trans  = (const float*)d_in[5];
    float* out = (float*)d_out;

    gemm_emis_kernel<<<BB * TT / 128, 256>>>(hidden, Wm, bias);
    crf_kernel<<<BB, 320>>>(masks, target, trans, out, out + (size_t)BB * TT);
}

// round 6
// speedup vs baseline: 1.0477x; 1.0477x over previous
#include <cuda_runtime.h>
#include <cuda_bf16.h>
#include <math.h>

#define BB 128
#define TT 256
#define HH 768
#define KK 64

typedef unsigned long long u64t;

__device__ float g_emis[BB * TT * KK];   // emissions scratch, 8 MB

// ---- packed f32x2 helpers ------------------------------------------------
__device__ __forceinline__ u64t ffma2(u64t a, u64t b, u64t c) {
    u64t d;
    asm("fma.rn.f32x2 %0, %1, %2, %3;" : "=l"(d) : "l"(a), "l"(b), "l"(c));
    return d;
}
__device__ __forceinline__ u64t pack2(float lo, float hi) {
    u64t d;
    unsigned a = __float_as_uint(lo), b = __float_as_uint(hi);
    asm("mov.b64 %0, {%1, %2};" : "=l"(d) : "r"(a), "r"(b));
    return d;
}
__device__ __forceinline__ void unpack2(u64t v, float* lo, float* hi) {
    unsigned a, b;
    asm("mov.b64 {%0, %1}, %2;" : "=r"(a), "=r"(b) : "l"(v));
    *lo = __uint_as_float(a);
    *hi = __uint_as_float(b);
}

// ---------------------------------------------------------------------------
// Kernel 1: emissions = hidden @ W + b (unchanged; near FFMA2 pacing floor)
// ---------------------------------------------------------------------------
__global__ __launch_bounds__(256) void gemm_emis_kernel(
    const float* __restrict__ A,
    const float* __restrict__ Wm,
    const float* __restrict__ bias)
{
    __shared__ float As[16][132];
    __shared__ float Bs[16][64];

    const int tid = threadIdx.x;
    const int m0 = blockIdx.x * 128;
    const int ty = tid >> 4;
    const int tx = tid & 15;

    u64t acc2[4][4];
#pragma unroll
    for (int rp = 0; rp < 4; rp++)
#pragma unroll
        for (int c = 0; c < 4; c++) acc2[rp][c] = 0ull;

    const int arow0 = (tid) >> 2,       ac40 = (tid) & 3;
    const int arow1 = (tid + 256) >> 2, ac41 = (tid + 256) & 3;
    const int brow = tid >> 4, bc4 = tid & 15;

    float4 aReg0 = *(const float4*)&A[(size_t)(m0 + arow0) * HH + ac40 * 4];
    float4 aReg1 = *(const float4*)&A[(size_t)(m0 + arow1) * HH + ac41 * 4];
    float4 bReg  = *(const float4*)&Wm[(size_t)(brow) * KK + bc4 * 4];

    for (int kt = 0; kt < HH; kt += 16) {
        As[ac40 * 4 + 0][arow0] = aReg0.x;
        As[ac40 * 4 + 1][arow0] = aReg0.y;
        As[ac40 * 4 + 2][arow0] = aReg0.z;
        As[ac40 * 4 + 3][arow0] = aReg0.w;
        As[ac41 * 4 + 0][arow1] = aReg1.x;
        As[ac41 * 4 + 1][arow1] = aReg1.y;
        As[ac41 * 4 + 2][arow1] = aReg1.z;
        As[ac41 * 4 + 3][arow1] = aReg1.w;
        *(float4*)&Bs[brow][bc4 * 4] = bReg;
        __syncthreads();

        if (kt + 16 < HH) {
            aReg0 = *(const float4*)&A[(size_t)(m0 + arow0) * HH + kt + 16 + ac40 * 4];
            aReg1 = *(const float4*)&A[(size_t)(m0 + arow1) * HH + kt + 16 + ac41 * 4];
            bReg  = *(const float4*)&Wm[(size_t)(kt + 16 + brow) * KK + bc4 * 4];
        }

#pragma unroll
        for (int kk = 0; kk < 16; kk++) {
            const u64t* ap = (const u64t*)&As[kk][ty * 8];
            u64t a2[4];
#pragma unroll
            for (int rp = 0; rp < 4; rp++) a2[rp] = ap[rp];
            float4 bv = *(const float4*)&Bs[kk][tx * 4];
            u64t bd[4];
            bd[0] = pack2(bv.x, bv.x);
            bd[1] = pack2(bv.y, bv.y);
            bd[2] = pack2(bv.z, bv.z);
            bd[3] = pack2(bv.w, bv.w);
#pragma unroll
            for (int rp = 0; rp < 4; rp++)
#pragma unroll
                for (int c = 0; c < 4; c++)
                    acc2[rp][c] = ffma2(a2[rp], bd[c], acc2[rp][c]);
        }
        __syncthreads();
    }

    float4 bb = *(const float4*)&bias[tx * 4];
    const float bbv[4] = {bb.x, bb.y, bb.z, bb.w};
#pragma unroll
    for (int rp = 0; rp < 4; rp++) {
        float o0[4], o1[4];
#pragma unroll
        for (int c = 0; c < 4; c++) {
            float lo, hi;
            unpack2(acc2[rp][c], &lo, &hi);
            o0[c] = lo + bbv[c];
            o1[c] = hi + bbv[c];
        }
        int row = m0 + ty * 8 + 2 * rp;
        *(float4*)&g_emis[(size_t)row * KK + tx * 4]       = make_float4(o0[0], o0[1], o0[2], o0[3]);
        *(float4*)&g_emis[(size_t)(row + 1) * KK + tx * 4] = make_float4(o1[0], o1[1], o1[2], o1[3]);
    }
}

// ---------------------------------------------------------------------------
// Kernel 2: CRF. grid=128 (one wave), 320 threads:
//   warps 0..7  (tid 0..255):  Viterbi, 4 threads/state, bar.sync 1,256.
//     - deep emission prefetch (4-step chunks, distance 4..7)
//     - FMNMX-only value critical path; argmax index deferred one step
//   warps 8..9  (tid 256..319): forward log-norm + seq_score, bar.sync 2,64.
//     - deep prefetch + __expf precomputed a chunk ahead (off-chain)
// ---------------------------------------------------------------------------
__global__ __launch_bounds__(320) void crf_kernel(
    const int* __restrict__ masks,
    const int* __restrict__ target,
    const float* __restrict__ trans_g,
    float* __restrict__ out_dec,
    float* __restrict__ out_ll)
{
    __shared__ __align__(16) float s_v[2][64];     // viterbi values
    __shared__ __align__(16) float s_P[2][64];     // forward probs
    __shared__ float s_red[4];
    __shared__ int s_len_v, s_len_f;
    __shared__ int s_path[TT];
    __shared__ unsigned char s_bp[(TT - 1) * KK];

    const int tid = threadIdx.x;
    const int b = blockIdx.x;
    const float* emisb = &g_emis[(size_t)b * TT * KK];

    if (tid < 256) {
        // ================= VITERBI: 8 warps, 4 threads per state ============
        if (tid < 32) {
            int acc = 0;
#pragma unroll
            for (int i = 0; i < 8; i++) acc += masks[b * TT + tid + 32 * i];
#pragma unroll
            for (int o = 16; o; o >>= 1) acc += __shfl_xor_sync(0xFFFFFFFFu, acc, o);
            if (tid == 0) s_len_v = acc;
        }

        const int j = tid >> 2;      // state 0..63
        const int q = tid & 3;       // quarter 0..3
        const int k0 = q * 16;

        float Tcol[16];
#pragma unroll
        for (int kk = 0; kk < 16; kk++)
            Tcol[kk] = trans_g[(k0 + kk) * KK + j];

        float e0 = emisb[j];
        float ecur[4];
#pragma unroll
        for (int i = 0; i < 4; i++) ecur[i] = emisb[(size_t)(1 + i) * KK + j];

        float prevV = e0;
        if (q == 0) s_v[0][j] = e0;
        asm volatile("bar.sync 1, 256;" ::: "memory");
        const int len = s_len_v;
        int buf = 0;

        // deferred-argmax pending state
        float pa[16];
        float pbv = 0.f;
        int pvalid = 0;    // 0=no pending, 1=resolve argmax, 2=identity bp
        int pt = 0;

        for (int tb = 1; tb < TT; tb += 4) {
            // chunk prefetch (distance 4..7 steps)
            float enext[4];
#pragma unroll
            for (int i = 0; i < 4; i++) {
                int tt = tb + 4 + i;
                enext[i] = (tt < TT) ? emisb[(size_t)tt * KK + j] : 0.f;
            }
#pragma unroll
            for (int i = 0; i < 4; i++) {
                const int t = tb + i;
                if (t >= TT) break;   // uniform

                // ---- resolve pending backpointer from previous step ----
                if (pvalid) {
                    int li;
                    if (pvalid == 1) {
                        int lm = 16;
#pragma unroll
                        for (int m = 15; m >= 0; m--)
                            lm = (pa[m] == pbv) ? m : lm;     // first match wins
                        li = (lm == 16) ? 1000 : (k0 + lm);
                        int oi = __shfl_xor_sync(0xFFFFFFFFu, li, 1);
                        li = min(li, oi);
                        oi = __shfl_xor_sync(0xFFFFFFFFu, li, 2);
                        li = min(li, oi);
                    } else {
                        li = j;
                    }
                    if (q == 0) s_bp[(pt - 1) * KK + j] = (unsigned char)li;
                }

                // ---- value phase (critical path, FMNMX only) ----
                const float4* V4 = (const float4*)&s_v[buf][k0];
                float4 v0 = V4[0], v1 = V4[1], v2 = V4[2], v3 = V4[3];
                float a[16];
                a[0]  = v0.x + Tcol[0];  a[1]  = v0.y + Tcol[1];
                a[2]  = v0.z + Tcol[2];  a[3]  = v0.w + Tcol[3];
                a[4]  = v1.x + Tcol[4];  a[5]  = v1.y + Tcol[5];
                a[6]  = v1.z + Tcol[6];  a[7]  = v1.w + Tcol[7];
                a[8]  = v2.x + Tcol[8];  a[9]  = v2.y + Tcol[9];
                a[10] = v2.z + Tcol[10]; a[11] = v2.w + Tcol[11];
                a[12] = v3.x + Tcol[12]; a[13] = v3.y + Tcol[13];
                a[14] = v3.z + Tcol[14]; a[15] = v3.w + Tcol[15];

                float m0 = fmaxf(a[0], a[1]),   m1 = fmaxf(a[2], a[3]);
                float m2 = fmaxf(a[4], a[5]),   m3 = fmaxf(a[6], a[7]);
                float m4 = fmaxf(a[8], a[9]),   m5 = fmaxf(a[10], a[11]);
                float m6 = fmaxf(a[12], a[13]), m7 = fmaxf(a[14], a[15]);
                m0 = fmaxf(m0, m1); m2 = fmaxf(m2, m3);
                m4 = fmaxf(m4, m5); m6 = fmaxf(m6, m7);
                m0 = fmaxf(m0, m2); m4 = fmaxf(m4, m6);
                float bv = fmaxf(m0, m4);
                bv = fmaxf(bv, __shfl_xor_sync(0xFFFFFFFFu, bv, 1));
                bv = fmaxf(bv, __shfl_xor_sync(0xFFFFFFFFu, bv, 2));

                float newv = (t < len) ? (bv + ecur[i]) : prevV;
                if (q == 0) s_v[buf ^ 1][j] = newv;
                prevV = newv;

                // stash pending argmax work
#pragma unroll
                for (int m = 0; m < 16; m++) pa[m] = a[m];
                pbv = bv;
                pvalid = (t < len) ? 1 : 2;
                pt = t;

                asm volatile("bar.sync 1, 256;" ::: "memory");
                buf ^= 1;
            }
#pragma unroll
            for (int i = 0; i < 4; i++) ecur[i] = enext[i];
        }

        // resolve final pending bp (t = 255)
        {
            int li;
            if (pvalid == 1) {
                int lm = 16;
#pragma unroll
                for (int m = 15; m >= 0; m--)
                    lm = (pa[m] == pbv) ? m : lm;
                li = (lm == 16) ? 1000 : (k0 + lm);
                int oi = __shfl_xor_sync(0xFFFFFFFFu, li, 1);
                li = min(li, oi);
                oi = __shfl_xor_sync(0xFFFFFFFFu, li, 2);
                li = min(li, oi);
            } else {
                li = j;
            }
            if (q == 0) s_bp[(pt - 1) * KK + j] = (unsigned char)li;
        }
        asm volatile("bar.sync 1, 256;" ::: "memory");

        if (tid == 0) {
            float bvv = s_v[buf][0];
            int tg = 0;
#pragma unroll
            for (int k = 1; k < KK; k++)
                if (s_v[buf][k] > bvv) { bvv = s_v[buf][k]; tg = k; }
            s_path[TT - 1] = tg;
            for (int t = TT - 1; t >= 1; t--) {
                tg = s_bp[(t - 1) * KK + tg];
                s_path[t - 1] = tg;
            }
        }
        asm volatile("bar.sync 1, 256;" ::: "memory");
        out_dec[(size_t)b * TT + tid] = (float)((tid < len) ? s_path[tid] : 0);

    } else {
        // ================= FORWARD: 2 warps (tid 256..319) =================
        const int ft = tid - 256;     // 0..63

        if (ft < 32) {
            int acc = 0;
#pragma unroll
            for (int i = 0; i < 8; i++) acc += masks[b * TT + ft + 32 * i];
#pragma unroll
            for (int o = 16; o; o >>= 1) acc += __shfl_xor_sync(0xFFFFFFFFu, acc, o);
            if (ft == 0) s_len_f = acc;
        }

        const int j = ft;
        u64t E2[32];
#pragma unroll
        for (int m = 0; m < 32; m++) {
            float t0 = trans_g[(2 * m) * KK + j];
            float t1 = trans_g[(2 * m + 1) * KK + j];
            E2[m] = pack2(expf(t0), expf(t1));
        }

        float e0 = emisb[j];
        float ecur[4];
#pragma unroll
        for (int i = 0; i < 4; i++) ecur[i] = emisb[(size_t)(1 + i) * KK + j];

        float prevP = __expf(e0);
        int iexp = 0;
        s_P[0][j] = prevP;
        asm volatile("bar.sync 2, 64;" ::: "memory");
        const int len = s_len_f;
        int buf = 0;

        for (int tb = 1; tb < TT; tb += 4) {
            float enext[4];
#pragma unroll
            for (int i = 0; i < 4; i++) {
                int tt = tb + 4 + i;
                enext[i] = (tt < TT) ? emisb[(size_t)tt * KK + j] : 0.f;
            }
            // exps of current chunk (data loaded a chunk ago -> off-chain)
            float eexp[4];
#pragma unroll
            for (int i = 0; i < 4; i++) eexp[i] = __expf(ecur[i]);

#pragma unroll
            for (int i = 0; i < 4; i++) {
                const int t = tb + i;
                if (t >= TT) break;   // uniform

                float p0 = s_P[buf][0];
                const float4* P4 = (const float4*)&s_P[buf][0];
                u64t s0 = 0ull, s1 = 0ull, s2 = 0ull, s3 = 0ull;
#pragma unroll
                for (int m = 0; m < 4; m++) {
                    float4 pA = P4[4 * m + 0];
                    float4 pB = P4[4 * m + 1];
                    float4 pC = P4[4 * m + 2];
                    float4 pD = P4[4 * m + 3];
                    s0 = ffma2(pack2(pA.x, pA.y), E2[8 * m + 0], s0);
                    s0 = ffma2(pack2(pA.z, pA.w), E2[8 * m + 1], s0);
                    s1 = ffma2(pack2(pB.x, pB.y), E2[8 * m + 2], s1);
                    s1 = ffma2(pack2(pB.z, pB.w), E2[8 * m + 3], s1);
                    s2 = ffma2(pack2(pC.x, pC.y), E2[8 * m + 4], s2);
                    s2 = ffma2(pack2(pC.z, pC.w), E2[8 * m + 5], s2);
                    s3 = ffma2(pack2(pD.x, pD.y), E2[8 * m + 6], s3);
                    s3 = ffma2(pack2(pD.z, pD.w), E2[8 * m + 7], s3);
                }
                float l0, h0, l1, h1, l2, h2, l3, h3;
                unpack2(s0, &l0, &h0);
                unpack2(s1, &l1, &h1);
                unpack2(s2, &l2, &h2);
                unpack2(s3, &l3, &h3);
                float S = ((l0 + h0) + (l1 + h1)) + ((l2 + h2) + (l3 + h3));

                // exact power-of-2 rescale by p0's exponent
                int e0i = (int)(__float_as_uint(p0) >> 23);
                float scale = __uint_as_float((unsigned)(254 - e0i) << 23);
                if (t < len) {
                    prevP = S * scale * eexp[i];
                    iexp += e0i - 127;
                }
                s_P[buf ^ 1][j] = prevP;
                asm volatile("bar.sync 2, 64;" ::: "memory");
                buf ^= 1;
            }
#pragma unroll
            for (int i = 0; i < 4; i++) ecur[i] = enext[i];
        }

        // log_norm: sum final P across 64 threads
        float sp = prevP;
#pragma unroll
        for (int o = 16; o; o >>= 1) sp += __shfl_xor_sync(0xFFFFFFFFu, sp, o);
        if ((ft & 31) == 0) s_red[ft >> 5] = sp;

        // seq_score partials: 4 t's per thread
        float uacc = 0.f;
#pragma unroll
        for (int i = 0; i < 4; i++) {
            int tt = ft + 64 * i;
            if (tt < len) {
                int tg = target[b * TT + tt];
                uacc += emisb[(size_t)tt * KK + tg];
                if (tt >= 1) uacc += trans_g[target[b * TT + tt - 1] * KK + tg];
            }
        }
#pragma unroll
        for (int o = 16; o; o >>= 1) uacc += __shfl_xor_sync(0xFFFFFFFFu, uacc, o);
        if ((ft & 31) == 0) s_red[2 + (ft >> 5)] = uacc;
        asm volatile("bar.sync 2, 64;" ::: "memory");

        if (ft == 0) {
            float sumP = s_red[0] + s_red[1];
            float score = s_red[2] + s_red[3];
            const float LN2 = 0.69314718055994531f;
            out_ll[b] = score - ((float)iexp * LN2 + logf(sumP));
        }
    }
}

// ---------------------------------------------------------------------------
extern "C" void kernel_launch(void* const* d_in, const int* in_sizes, int n_in,
                              void* d_out, int out_size) {
    const float* hidden = (const float*)d_in[0];
    const int*   masks  = (const int*)d_in[1];
    const int*   target = (const int*)d_in[2];
    const float* Wm     = (const float*)d_in[3];
    const float* bias   = (const float*)d_in[4];
    const float* trans  = (const float*)d_in[5];
    float* out = (float*)d_out;

    gemm_emis_kernel<<<BB * TT / 128, 256>>>(hidden, Wm, bias);
    crf_kernel<<<BB, 320>>>(masks, target, trans, out, out + (size_t)BB * TT);
}

// round 7
// speedup vs baseline: 1.1607x; 1.1078x over previous
#include <cuda_runtime.h>
#include <cuda_bf16.h>
#include <math.h>

#define BB 128
#define TT 256
#define HH 768
#define KK 64

typedef unsigned long long u64t;

__device__ float g_emis[BB * TT * KK];   // emissions scratch, 8 MB

// ---- packed f32x2 helpers ------------------------------------------------
__device__ __forceinline__ u64t ffma2(u64t a, u64t b, u64t c) {
    u64t d;
    asm("fma.rn.f32x2 %0, %1, %2, %3;" : "=l"(d) : "l"(a), "l"(b), "l"(c));
    return d;
}
__device__ __forceinline__ u64t pack2(float lo, float hi) {
    u64t d;
    unsigned a = __float_as_uint(lo), b = __float_as_uint(hi);
    asm("mov.b64 %0, {%1, %2};" : "=l"(d) : "r"(a), "r"(b));
    return d;
}
__device__ __forceinline__ void unpack2(u64t v, float* lo, float* hi) {
    unsigned a, b;
    asm("mov.b64 {%0, %1}, %2;" : "=r"(a), "=r"(b) : "l"(v));
    *lo = __uint_as_float(a);
    *hi = __uint_as_float(b);
}

// ---------------------------------------------------------------------------
// Kernel 1: emissions = hidden @ W + b (unchanged; ~95% of f32 FFMA2 peak)
// ---------------------------------------------------------------------------
__global__ __launch_bounds__(256) void gemm_emis_kernel(
    const float* __restrict__ A,
    const float* __restrict__ Wm,
    const float* __restrict__ bias)
{
    __shared__ float As[16][132];
    __shared__ float Bs[16][64];

    const int tid = threadIdx.x;
    const int m0 = blockIdx.x * 128;
    const int ty = tid >> 4;
    const int tx = tid & 15;

    u64t acc2[4][4];
#pragma unroll
    for (int rp = 0; rp < 4; rp++)
#pragma unroll
        for (int c = 0; c < 4; c++) acc2[rp][c] = 0ull;

    const int arow0 = (tid) >> 2,       ac40 = (tid) & 3;
    const int arow1 = (tid + 256) >> 2, ac41 = (tid + 256) & 3;
    const int brow = tid >> 4, bc4 = tid & 15;

    float4 aReg0 = *(const float4*)&A[(size_t)(m0 + arow0) * HH + ac40 * 4];
    float4 aReg1 = *(const float4*)&A[(size_t)(m0 + arow1) * HH + ac41 * 4];
    float4 bReg  = *(const float4*)&Wm[(size_t)(brow) * KK + bc4 * 4];

    for (int kt = 0; kt < HH; kt += 16) {
        As[ac40 * 4 + 0][arow0] = aReg0.x;
        As[ac40 * 4 + 1][arow0] = aReg0.y;
        As[ac40 * 4 + 2][arow0] = aReg0.z;
        As[ac40 * 4 + 3][arow0] = aReg0.w;
        As[ac41 * 4 + 0][arow1] = aReg1.x;
        As[ac41 * 4 + 1][arow1] = aReg1.y;
        As[ac41 * 4 + 2][arow1] = aReg1.z;
        As[ac41 * 4 + 3][arow1] = aReg1.w;
        *(float4*)&Bs[brow][bc4 * 4] = bReg;
        __syncthreads();

        if (kt + 16 < HH) {
            aReg0 = *(const float4*)&A[(size_t)(m0 + arow0) * HH + kt + 16 + ac40 * 4];
            aReg1 = *(const float4*)&A[(size_t)(m0 + arow1) * HH + kt + 16 + ac41 * 4];
            bReg  = *(const float4*)&Wm[(size_t)(kt + 16 + brow) * KK + bc4 * 4];
        }

#pragma unroll
        for (int kk = 0; kk < 16; kk++) {
            const u64t* ap = (const u64t*)&As[kk][ty * 8];
            u64t a2[4];
#pragma unroll
            for (int rp = 0; rp < 4; rp++) a2[rp] = ap[rp];
            float4 bv = *(const float4*)&Bs[kk][tx * 4];
            u64t bd[4];
            bd[0] = pack2(bv.x, bv.x);
            bd[1] = pack2(bv.y, bv.y);
            bd[2] = pack2(bv.z, bv.z);
            bd[3] = pack2(bv.w, bv.w);
#pragma unroll
            for (int rp = 0; rp < 4; rp++)
#pragma unroll
                for (int c = 0; c < 4; c++)
                    acc2[rp][c] = ffma2(a2[rp], bd[c], acc2[rp][c]);
        }
        __syncthreads();
    }

    float4 bb = *(const float4*)&bias[tx * 4];
    const float bbv[4] = {bb.x, bb.y, bb.z, bb.w};
#pragma unroll
    for (int rp = 0; rp < 4; rp++) {
        float o0[4], o1[4];
#pragma unroll
        for (int c = 0; c < 4; c++) {
            float lo, hi;
            unpack2(acc2[rp][c], &lo, &hi);
            o0[c] = lo + bbv[c];
            o1[c] = hi + bbv[c];
        }
        int row = m0 + ty * 8 + 2 * rp;
        *(float4*)&g_emis[(size_t)row * KK + tx * 4]       = make_float4(o0[0], o0[1], o0[2], o0[3]);
        *(float4*)&g_emis[(size_t)(row + 1) * KK + tx * 4] = make_float4(o1[0], o1[1], o1[2], o1[3]);
    }
}

// ---------------------------------------------------------------------------
// Kernel 2: CRF. grid=128 (one block/SM), 192 threads:
//   tid 0..127  : Viterbi, 2 threads/state, bar.sync 1,128.
//     - triple-buffered s_v, deep emission prefetch (4-step chunks)
//     - FMNMX-only value path, quad maxes kept; argmax deferred 1 step and
//       resolved by quad-scan + single-quad bit-exact recompute from the
//       still-intact old buffer (triple buffering guarantees safety)
//   tid 128..191: forward log-norm + seq_score, bar.sync 2,64.
// ---------------------------------------------------------------------------
__global__ __launch_bounds__(192) void crf_kernel(
    const int* __restrict__ masks,
    const int* __restrict__ target,
    const float* __restrict__ trans_g,
    float* __restrict__ out_dec,
    float* __restrict__ out_ll)
{
    __shared__ __align__(16) float s_v[3][64];     // viterbi values (triple buf)
    __shared__ __align__(16) float s_P[2][64];     // forward probs
    __shared__ __align__(16) float s_tt[64 * 68];  // trans transposed, row pad 68
    __shared__ float s_red[4];
    __shared__ int s_len_v, s_len_f;
    __shared__ int s_path[TT];
    __shared__ unsigned char s_bp[(TT - 1) * KK];

    const int tid = threadIdx.x;
    const int b = blockIdx.x;
    const float* emisb = &g_emis[(size_t)b * TT * KK];

    if (tid < 128) {
        // ================= VITERBI: 4 warps, 2 threads per state ============
        if (tid < 32) {
            int acc = 0;
#pragma unroll
            for (int i = 0; i < 8; i++) acc += masks[b * TT + tid + 32 * i];
#pragma unroll
            for (int o = 16; o; o >>= 1) acc += __shfl_xor_sync(0xFFFFFFFFu, acc, o);
            if (tid == 0) s_len_v = acc;
        }

        const int j = tid >> 1;      // state 0..63
        const int h = tid & 1;       // half 0..1
        const int k0 = h * 32;

        // transposed transition matrix into smem: s_tt[j][k] = trans[k][j]
        for (int i = tid; i < 4096; i += 128) {
            int k = i >> 6, jj = i & 63;
            s_tt[jj * 68 + k] = trans_g[i];
        }

        // register half-column
        float Tcol[32];
#pragma unroll
        for (int kk = 0; kk < 32; kk++)
            Tcol[kk] = trans_g[(k0 + kk) * KK + j];

        float e0 = emisb[j];
        float ecur[4];
#pragma unroll
        for (int i = 0; i < 4; i++) ecur[i] = emisb[(size_t)(1 + i) * KK + j];

        float prevV = e0;
        if (h == 0) s_v[0][j] = e0;
        asm volatile("bar.sync 1, 128;" ::: "memory");
        const int len = s_len_v;
        int rbuf = 0;

        // deferred-argmax pending state: 8 quad maxes + global max
        float pqm[8];
        float pbv = 0.f;
        int pvalid = 0;    // 0=none, 1=resolve, 2=identity
        int pt = 0;

        for (int tb = 1; tb < TT; tb += 4) {
            // chunk emission prefetch (distance 4..7 steps)
            float enext[4];
#pragma unroll
            for (int i = 0; i < 4; i++) {
                int tt = tb + 4 + i;
                enext[i] = (tt < TT) ? emisb[(size_t)tt * KK + j] : 0.f;
            }
#pragma unroll
            for (int i = 0; i < 4; i++) {
                const int t = tb + i;
                if (t >= TT) break;   // uniform

                const int wbuf = (rbuf == 2) ? 0 : rbuf + 1;
                const int obuf = (wbuf == 2) ? 0 : wbuf + 1;  // = (rbuf+2)%3

                // ---- resolve pending backpointer (reads OLD buffer obuf) ---
                if (pvalid) {
                    int li = 255;
                    if (pvalid == 1) {
                        int qq = 8;
#pragma unroll
                        for (int m = 7; m >= 0; m--)
                            qq = (pqm[m] == pbv) ? m : qq;    // first quad wins
                        if (qq < 8) {
                            int kq = k0 + qq * 4;
                            float4 vq = *(const float4*)&s_v[obuf][kq];
                            float4 tq = *(const float4*)&s_tt[j * 68 + kq];
                            float c0 = vq.x + tq.x, c1 = vq.y + tq.y;
                            float c2 = vq.z + tq.z, c3 = vq.w + tq.w;
                            li = kq + 3;
                            li = (c2 == pbv) ? kq + 2 : li;
                            li = (c1 == pbv) ? kq + 1 : li;
                            li = (c0 == pbv) ? kq : li;
                        }
                        int oi = __shfl_xor_sync(0xFFFFFFFFu, li, 1);
                        li = min(li, oi);
                    } else {
                        li = j;
                    }
                    if (h == 0) s_bp[(pt - 1) * KK + j] = (unsigned char)li;
                }

                // ---- value phase (FMNMX only on the critical path) ----
                const float4* V4 = (const float4*)&s_v[rbuf][k0];
                float qm[8];
#pragma unroll
                for (int q = 0; q < 8; q++) {
                    float4 v4 = V4[q];
                    float c0 = v4.x + Tcol[4 * q + 0];
                    float c1 = v4.y + Tcol[4 * q + 1];
                    float c2 = v4.z + Tcol[4 * q + 2];
                    float c3 = v4.w + Tcol[4 * q + 3];
                    qm[q] = fmaxf(fmaxf(c0, c1), fmaxf(c2, c3));
                }
                float m0 = fmaxf(qm[0], qm[1]), m1 = fmaxf(qm[2], qm[3]);
                float m2 = fmaxf(qm[4], qm[5]), m3 = fmaxf(qm[6], qm[7]);
                float bv = fmaxf(fmaxf(m0, m1), fmaxf(m2, m3));
                bv = fmaxf(bv, __shfl_xor_sync(0xFFFFFFFFu, bv, 1));

                float newv = (t < len) ? (bv + ecur[i]) : prevV;
                if (h == 0) s_v[wbuf][j] = newv;
                prevV = newv;

                // stash pending argmax state
#pragma unroll
                for (int m = 0; m < 8; m++) pqm[m] = qm[m];
                pbv = bv;
                pvalid = (t < len) ? 1 : 2;
                pt = t;

                asm volatile("bar.sync 1, 128;" ::: "memory");
                rbuf = wbuf;
            }
#pragma unroll
            for (int i = 0; i < 4; i++) ecur[i] = enext[i];
        }

        // final pending bp (t = 255); old buffer = (rbuf+2)%3
        {
            const int obuf = (rbuf == 0) ? 2 : rbuf - 1;  // buffer read at t=255
            int li = 255;
            if (pvalid == 1) {
                int qq = 8;
#pragma unroll
                for (int m = 7; m >= 0; m--)
                    qq = (pqm[m] == pbv) ? m : qq;
                if (qq < 8) {
                    int kq = k0 + qq * 4;
                    float4 vq = *(const float4*)&s_v[obuf][kq];
                    float4 tq = *(const float4*)&s_tt[j * 68 + kq];
                    float c0 = vq.x + tq.x, c1 = vq.y + tq.y;
                    float c2 = vq.z + tq.z, c3 = vq.w + tq.w;
                    li = kq + 3;
                    li = (c2 == pbv) ? kq + 2 : li;
                    li = (c1 == pbv) ? kq + 1 : li;
                    li = (c0 == pbv) ? kq : li;
                }
                int oi = __shfl_xor_sync(0xFFFFFFFFu, li, 1);
                li = min(li, oi);
            } else {
                li = j;
            }
            if (h == 0) s_bp[(pt - 1) * KK + j] = (unsigned char)li;
        }
        asm volatile("bar.sync 1, 128;" ::: "memory");

        if (tid == 0) {
            float bvv = s_v[rbuf][0];
            int tg = 0;
#pragma unroll
            for (int k = 1; k < KK; k++)
                if (s_v[rbuf][k] > bvv) { bvv = s_v[rbuf][k]; tg = k; }
            s_path[TT - 1] = tg;
            for (int t = TT - 1; t >= 1; t--) {
                tg = s_bp[(t - 1) * KK + tg];
                s_path[t - 1] = tg;
            }
        }
        asm volatile("bar.sync 1, 128;" ::: "memory");
#pragma unroll
        for (int i = 0; i < 2; i++) {
            int tt = tid + 128 * i;
            out_dec[(size_t)b * TT + tt] = (float)((tt < len) ? s_path[tt] : 0);
        }

    } else {
        // ================= FORWARD: 2 warps (tid 128..191) =================
        const int ft = tid - 128;     // 0..63

        if (ft < 32) {
            int acc = 0;
#pragma unroll
            for (int i = 0; i < 8; i++) acc += masks[b * TT + ft + 32 * i];
#pragma unroll
            for (int o = 16; o; o >>= 1) acc += __shfl_xor_sync(0xFFFFFFFFu, acc, o);
            if (ft == 0) s_len_f = acc;
        }

        const int j = ft;
        u64t E2[32];
#pragma unroll
        for (int m = 0; m < 32; m++) {
            float t0 = trans_g[(2 * m) * KK + j];
            float t1 = trans_g[(2 * m + 1) * KK + j];
            E2[m] = pack2(expf(t0), expf(t1));
        }

        float e0 = emisb[j];
        float ecur[4];
#pragma unroll
        for (int i = 0; i < 4; i++) ecur[i] = emisb[(size_t)(1 + i) * KK + j];

        float prevP = __expf(e0);
        int iexp = 0;
        s_P[0][j] = prevP;
        asm volatile("bar.sync 2, 64;" ::: "memory");
        const int len = s_len_f;
        int buf = 0;

        for (int tb = 1; tb < TT; tb += 4) {
            float enext[4];
#pragma unroll
            for (int i = 0; i < 4; i++) {
                int tt = tb + 4 + i;
                enext[i] = (tt < TT) ? emisb[(size_t)tt * KK + j] : 0.f;
            }
            float eexp[4];
#pragma unroll
            for (int i = 0; i < 4; i++) eexp[i] = __expf(ecur[i]);

#pragma unroll
            for (int i = 0; i < 4; i++) {
                const int t = tb + i;
                if (t >= TT) break;   // uniform

                float p0 = s_P[buf][0];
                const float4* P4 = (const float4*)&s_P[buf][0];
                u64t s0 = 0ull, s1 = 0ull, s2 = 0ull, s3 = 0ull;
#pragma unroll
                for (int m = 0; m < 4; m++) {
                    float4 pA = P4[4 * m + 0];
                    float4 pB = P4[4 * m + 1];
                    float4 pC = P4[4 * m + 2];
                    float4 pD = P4[4 * m + 3];
                    s0 = ffma2(pack2(pA.x, pA.y), E2[8 * m + 0], s0);
                    s0 = ffma2(pack2(pA.z, pA.w), E2[8 * m + 1], s0);
                    s1 = ffma2(pack2(pB.x, pB.y), E2[8 * m + 2], s1);
                    s1 = ffma2(pack2(pB.z, pB.w), E2[8 * m + 3], s1);
                    s2 = ffma2(pack2(pC.x, pC.y), E2[8 * m + 4], s2);
                    s2 = ffma2(pack2(pC.z, pC.w), E2[8 * m + 5], s2);
                    s3 = ffma2(pack2(pD.x, pD.y), E2[8 * m + 6], s3);
                    s3 = ffma2(pack2(pD.z, pD.w), E2[8 * m + 7], s3);
                }
                float l0, h0, l1, h1, l2, h2, l3, h3;
                unpack2(s0, &l0, &h0);
                unpack2(s1, &l1, &h1);
                unpack2(s2, &l2, &h2);
                unpack2(s3, &l3, &h3);
                float S = ((l0 + h0) + (l1 + h1)) + ((l2 + h2) + (l3 + h3));

                int e0i = (int)(__float_as_uint(p0) >> 23);
                float scale = __uint_as_float((unsigned)(254 - e0i) << 23);
                if (t < len) {
                    prevP = S * scale * eexp[i];
                    iexp += e0i - 127;
                }
                s_P[buf ^ 1][j] = prevP;
                asm volatile("bar.sync 2, 64;" ::: "memory");
                buf ^= 1;
            }
#pragma unroll
            for (int i = 0; i < 4; i++) ecur[i] = enext[i];
        }

        float sp = prevP;
#pragma unroll
        for (int o = 16; o; o >>= 1) sp += __shfl_xor_sync(0xFFFFFFFFu, sp, o);
        if ((ft & 31) == 0) s_red[ft >> 5] = sp;

        float uacc = 0.f;
#pragma unroll
        for (int i = 0; i < 4; i++) {
            int tt = ft + 64 * i;
            if (tt < len) {
                int tg = target[b * TT + tt];
                uacc += emisb[(size_t)tt * KK + tg];
                if (tt >= 1) uacc += trans_g[target[b * TT + tt - 1] * KK + tg];
            }
        }
#pragma unroll
        for (int o = 16; o; o >>= 1) uacc += __shfl_xor_sync(0xFFFFFFFFu, uacc, o);
        if ((ft & 31) == 0) s_red[2 + (ft >> 5)] = uacc;
        asm volatile("bar.sync 2, 64;" ::: "memory");

        if (ft == 0) {
            float sumP = s_red[0] + s_red[1];
            float score = s_red[2] + s_red[3];
            const float LN2 = 0.69314718055994531f;
            out_ll[b] = score - ((float)iexp * LN2 + logf(sumP));
        }
    }
}

// ---------------------------------------------------------------------------
extern "C" void kernel_launch(void* const* d_in, const int* in_sizes, int n_in,
                              void* d_out, int out_size) {
    const float* hidden = (const float*)d_in[0];
    const int*   masks  = (const int*)d_in[1];
    const int*   target = (const int*)d_in[2];
    const float* Wm     = (const float*)d_in[3];
    const float* bias   = (const float*)d_in[4];
    const float* trans  = (const float*)d_in[5];
    float* out = (float*)d_out;

    gemm_emis_kernel<<<BB * TT / 128, 256>>>(hidden, Wm, bias);
    crf_kernel<<<BB, 192>>>(masks, target, trans, out, out + (size_t)BB * TT);
}

// round 8
// speedup vs baseline: 1.1618x; 1.0010x over previous
#include <cuda_runtime.h>
#include <cuda_bf16.h>
#include <math.h>

#define BB 128
#define TT 256
#define HH 768
#define KK 64

typedef unsigned long long u64t;

__device__ float g_emis[BB * TT * KK];   // emissions scratch, 8 MB

// ---- packed f32x2 helpers ------------------------------------------------
__device__ __forceinline__ u64t ffma2(u64t a, u64t b, u64t c) {
    u64t d;
    asm("fma.rn.f32x2 %0, %1, %2, %3;" : "=l"(d) : "l"(a), "l"(b), "l"(c));
    return d;
}
__device__ __forceinline__ u64t pack2(float lo, float hi) {
    u64t d;
    unsigned a = __float_as_uint(lo), b = __float_as_uint(hi);
    asm("mov.b64 %0, {%1, %2};" : "=l"(d) : "r"(a), "r"(b));
    return d;
}
__device__ __forceinline__ void unpack2(u64t v, float* lo, float* hi) {
    unsigned a, b;
    asm("mov.b64 {%0, %1}, %2;" : "=r"(a), "=r"(b) : "l"(v));
    *lo = __uint_as_float(a);
    *hi = __uint_as_float(b);
}

// ---------------------------------------------------------------------------
// Kernel 1: emissions = hidden @ W + b (unchanged; ~95% of f32 FFMA2 peak)
// ---------------------------------------------------------------------------
__global__ __launch_bounds__(256) void gemm_emis_kernel(
    const float* __restrict__ A,
    const float* __restrict__ Wm,
    const float* __restrict__ bias)
{
    __shared__ float As[16][132];
    __shared__ float Bs[16][64];

    const int tid = threadIdx.x;
    const int m0 = blockIdx.x * 128;
    const int ty = tid >> 4;
    const int tx = tid & 15;

    u64t acc2[4][4];
#pragma unroll
    for (int rp = 0; rp < 4; rp++)
#pragma unroll
        for (int c = 0; c < 4; c++) acc2[rp][c] = 0ull;

    const int arow0 = (tid) >> 2,       ac40 = (tid) & 3;
    const int arow1 = (tid + 256) >> 2, ac41 = (tid + 256) & 3;
    const int brow = tid >> 4, bc4 = tid & 15;

    float4 aReg0 = *(const float4*)&A[(size_t)(m0 + arow0) * HH + ac40 * 4];
    float4 aReg1 = *(const float4*)&A[(size_t)(m0 + arow1) * HH + ac41 * 4];
    float4 bReg  = *(const float4*)&Wm[(size_t)(brow) * KK + bc4 * 4];

    for (int kt = 0; kt < HH; kt += 16) {
        As[ac40 * 4 + 0][arow0] = aReg0.x;
        As[ac40 * 4 + 1][arow0] = aReg0.y;
        As[ac40 * 4 + 2][arow0] = aReg0.z;
        As[ac40 * 4 + 3][arow0] = aReg0.w;
        As[ac41 * 4 + 0][arow1] = aReg1.x;
        As[ac41 * 4 + 1][arow1] = aReg1.y;
        As[ac41 * 4 + 2][arow1] = aReg1.z;
        As[ac41 * 4 + 3][arow1] = aReg1.w;
        *(float4*)&Bs[brow][bc4 * 4] = bReg;
        __syncthreads();

        if (kt + 16 < HH) {
            aReg0 = *(const float4*)&A[(size_t)(m0 + arow0) * HH + kt + 16 + ac40 * 4];
            aReg1 = *(const float4*)&A[(size_t)(m0 + arow1) * HH + kt + 16 + ac41 * 4];
            bReg  = *(const float4*)&Wm[(size_t)(kt + 16 + brow) * KK + bc4 * 4];
        }

#pragma unroll
        for (int kk = 0; kk < 16; kk++) {
            const u64t* ap = (const u64t*)&As[kk][ty * 8];
            u64t a2[4];
#pragma unroll
            for (int rp = 0; rp < 4; rp++) a2[rp] = ap[rp];
            float4 bv = *(const float4*)&Bs[kk][tx * 4];
            u64t bd[4];
            bd[0] = pack2(bv.x, bv.x);
            bd[1] = pack2(bv.y, bv.y);
            bd[2] = pack2(bv.z, bv.z);
            bd[3] = pack2(bv.w, bv.w);
#pragma unroll
            for (int rp = 0; rp < 4; rp++)
#pragma unroll
                for (int c = 0; c < 4; c++)
                    acc2[rp][c] = ffma2(a2[rp], bd[c], acc2[rp][c]);
        }
        __syncthreads();
    }

    float4 bb = *(const float4*)&bias[tx * 4];
    const float bbv[4] = {bb.x, bb.y, bb.z, bb.w};
#pragma unroll
    for (int rp = 0; rp < 4; rp++) {
        float o0[4], o1[4];
#pragma unroll
        for (int c = 0; c < 4; c++) {
            float lo, hi;
            unpack2(acc2[rp][c], &lo, &hi);
            o0[c] = lo + bbv[c];
            o1[c] = hi + bbv[c];
        }
        int row = m0 + ty * 8 + 2 * rp;
        *(float4*)&g_emis[(size_t)row * KK + tx * 4]       = make_float4(o0[0], o0[1], o0[2], o0[3]);
        *(float4*)&g_emis[(size_t)(row + 1) * KK + tx * 4] = make_float4(o1[0], o1[1], o1[2], o1[3]);
    }
}

// ---------------------------------------------------------------------------
// Kernel 2: CRF. grid=128, 256 threads = 8 warps, 1 vit + 1 fwd warp per SMSP:
//   tid 0..127  : Viterbi, 2 threads/state, bar.sync 1,128.
//     value-phase LDS issued FIRST; deferred argmax resolve runs in its
//     latency shadow (triple-buffered s_v keeps the old buffer intact).
//   tid 128..255: forward log-norm + seq_score, 2 threads/state (16 FFMA2 +
//     shfl-add combine), bar.sync 2,128.
// ---------------------------------------------------------------------------
__global__ __launch_bounds__(256) void crf_kernel(
    const int* __restrict__ masks,
    const int* __restrict__ target,
    const float* __restrict__ trans_g,
    float* __restrict__ out_dec,
    float* __restrict__ out_ll)
{
    __shared__ __align__(16) float s_v[3][64];     // viterbi values (triple buf)
    __shared__ __align__(16) float s_P[2][64];     // forward probs
    __shared__ __align__(16) float s_tt[64 * 68];  // trans transposed, row pad 68
    __shared__ float s_red[8];
    __shared__ int s_len_v, s_len_f;
    __shared__ int s_path[TT];
    __shared__ unsigned char s_bp[(TT - 1) * KK];

    const int tid = threadIdx.x;
    const int b = blockIdx.x;
    const float* emisb = &g_emis[(size_t)b * TT * KK];

    if (tid < 128) {
        // ================= VITERBI: 4 warps, 2 threads per state ============
        if (tid < 32) {
            int acc = 0;
#pragma unroll
            for (int i = 0; i < 8; i++) acc += masks[b * TT + tid + 32 * i];
#pragma unroll
            for (int o = 16; o; o >>= 1) acc += __shfl_xor_sync(0xFFFFFFFFu, acc, o);
            if (tid == 0) s_len_v = acc;
        }

        const int j = tid >> 1;      // state 0..63
        const int h = tid & 1;       // half 0..1
        const int k0 = h * 32;

        // transposed transition matrix: s_tt[j][k] = trans[k][j]
        for (int i = tid; i < 4096; i += 128) {
            int k = i >> 6, jj = i & 63;
            s_tt[jj * 68 + k] = trans_g[i];
        }

        float Tcol[32];
#pragma unroll
        for (int kk = 0; kk < 32; kk++)
            Tcol[kk] = trans_g[(k0 + kk) * KK + j];

        float e0 = emisb[j];
        float ecur[4];
#pragma unroll
        for (int i = 0; i < 4; i++) ecur[i] = emisb[(size_t)(1 + i) * KK + j];

        float prevV = e0;
        if (h == 0) s_v[0][j] = e0;
        asm volatile("bar.sync 1, 128;" ::: "memory");
        const int len = s_len_v;
        int rbuf = 0;

        // deferred-argmax pending state
        float pqm[8];
        float pbv = 0.f;
        int pvalid = 0;    // 0=none, 1=resolve, 2=identity
        int pt = 0;

        for (int tb = 1; tb < TT; tb += 4) {
            float enext[4];
#pragma unroll
            for (int i = 0; i < 4; i++) {
                int tt = tb + 4 + i;
                enext[i] = (tt < TT) ? emisb[(size_t)tt * KK + j] : 0.f;
            }
#pragma unroll
            for (int i = 0; i < 4; i++) {
                const int t = tb + i;
                if (t >= TT) break;   // uniform

                const int wbuf = (rbuf == 2) ? 0 : rbuf + 1;
                const int obuf = (wbuf == 2) ? 0 : wbuf + 1;  // old = (rbuf+2)%3

                // ---- ISSUE value-phase loads first (critical path) ----
                const float4* V4 = (const float4*)&s_v[rbuf][k0];
                float4 v0 = V4[0], v1 = V4[1], v2 = V4[2], v3 = V4[3];
                float4 v4 = V4[4], v5 = V4[5], v6 = V4[6], v7 = V4[7];

                // ---- resolve pending backpointer in the load shadow ----
                if (pvalid) {
                    int li = 255;
                    if (pvalid == 1) {
                        int qq = 8;
#pragma unroll
                        for (int m = 7; m >= 0; m--)
                            qq = (pqm[m] == pbv) ? m : qq;    // first quad wins
                        if (qq < 8) {
                            int kq = k0 + qq * 4;
                            float4 vq = *(const float4*)&s_v[obuf][kq];
                            float4 tq = *(const float4*)&s_tt[j * 68 + kq];
                            float c0 = vq.x + tq.x, c1 = vq.y + tq.y;
                            float c2 = vq.z + tq.z, c3 = vq.w + tq.w;
                            li = kq + 3;
                            li = (c2 == pbv) ? kq + 2 : li;
                            li = (c1 == pbv) ? kq + 1 : li;
                            li = (c0 == pbv) ? kq : li;
                        }
                        int oi = __shfl_xor_sync(0xFFFFFFFFu, li, 1);
                        li = min(li, oi);
                    } else {
                        li = j;
                    }
                    if (h == 0) s_bp[(pt - 1) * KK + j] = (unsigned char)li;
                }

                // ---- value phase (FMNMX only on the dependent chain) ----
                float qm[8];
                {
                    float c0, c1, c2, c3;
                    c0 = v0.x + Tcol[0];  c1 = v0.y + Tcol[1];
                    c2 = v0.z + Tcol[2];  c3 = v0.w + Tcol[3];
                    qm[0] = fmaxf(fmaxf(c0, c1), fmaxf(c2, c3));
                    c0 = v1.x + Tcol[4];  c1 = v1.y + Tcol[5];
                    c2 = v1.z + Tcol[6];  c3 = v1.w + Tcol[7];
                    qm[1] = fmaxf(fmaxf(c0, c1), fmaxf(c2, c3));
                    c0 = v2.x + Tcol[8];  c1 = v2.y + Tcol[9];
                    c2 = v2.z + Tcol[10]; c3 = v2.w + Tcol[11];
                    qm[2] = fmaxf(fmaxf(c0, c1), fmaxf(c2, c3));
                    c0 = v3.x + Tcol[12]; c1 = v3.y + Tcol[13];
                    c2 = v3.z + Tcol[14]; c3 = v3.w + Tcol[15];
                    qm[3] = fmaxf(fmaxf(c0, c1), fmaxf(c2, c3));
                    c0 = v4.x + Tcol[16]; c1 = v4.y + Tcol[17];
                    c2 = v4.z + Tcol[18]; c3 = v4.w + Tcol[19];
                    qm[4] = fmaxf(fmaxf(c0, c1), fmaxf(c2, c3));
                    c0 = v5.x + Tcol[20]; c1 = v5.y + Tcol[21];
                    c2 = v5.z + Tcol[22]; c3 = v5.w + Tcol[23];
                    qm[5] = fmaxf(fmaxf(c0, c1), fmaxf(c2, c3));
                    c0 = v6.x + Tcol[24]; c1 = v6.y + Tcol[25];
                    c2 = v6.z + Tcol[26]; c3 = v6.w + Tcol[27];
                    qm[6] = fmaxf(fmaxf(c0, c1), fmaxf(c2, c3));
                    c0 = v7.x + Tcol[28]; c1 = v7.y + Tcol[29];
                    c2 = v7.z + Tcol[30]; c3 = v7.w + Tcol[31];
                    qm[7] = fmaxf(fmaxf(c0, c1), fmaxf(c2, c3));
                }
                float m0 = fmaxf(qm[0], qm[1]), m1 = fmaxf(qm[2], qm[3]);
                float m2 = fmaxf(qm[4], qm[5]), m3 = fmaxf(qm[6], qm[7]);
                float bv = fmaxf(fmaxf(m0, m1), fmaxf(m2, m3));
                bv = fmaxf(bv, __shfl_xor_sync(0xFFFFFFFFu, bv, 1));

                float newv = (t < len) ? (bv + ecur[i]) : prevV;
                if (h == 0) s_v[wbuf][j] = newv;
                prevV = newv;

#pragma unroll
                for (int m = 0; m < 8; m++) pqm[m] = qm[m];
                pbv = bv;
                pvalid = (t < len) ? 1 : 2;
                pt = t;

                asm volatile("bar.sync 1, 128;" ::: "memory");
                rbuf = wbuf;
            }
#pragma unroll
            for (int i = 0; i < 4; i++) ecur[i] = enext[i];
        }

        // final pending bp (t = 255)
        {
            const int obuf = (rbuf == 0) ? 2 : rbuf - 1;
            int li = 255;
            if (pvalid == 1) {
                int qq = 8;
#pragma unroll
                for (int m = 7; m >= 0; m--)
                    qq = (pqm[m] == pbv) ? m : qq;
                if (qq < 8) {
                    int kq = k0 + qq * 4;
                    float4 vq = *(const float4*)&s_v[obuf][kq];
                    float4 tq = *(const float4*)&s_tt[j * 68 + kq];
                    float c0 = vq.x + tq.x, c1 = vq.y + tq.y;
                    float c2 = vq.z + tq.z, c3 = vq.w + tq.w;
                    li = kq + 3;
                    li = (c2 == pbv) ? kq + 2 : li;
                    li = (c1 == pbv) ? kq + 1 : li;
                    li = (c0 == pbv) ? kq : li;
                }
                int oi = __shfl_xor_sync(0xFFFFFFFFu, li, 1);
                li = min(li, oi);
            } else {
                li = j;
            }
            if (h == 0) s_bp[(pt - 1) * KK + j] = (unsigned char)li;
        }
        asm volatile("bar.sync 1, 128;" ::: "memory");

        if (tid == 0) {
            float bvv = s_v[rbuf][0];
            int tg = 0;
#pragma unroll
            for (int k = 1; k < KK; k++)
                if (s_v[rbuf][k] > bvv) { bvv = s_v[rbuf][k]; tg = k; }
            s_path[TT - 1] = tg;
            for (int t = TT - 1; t >= 1; t--) {
                tg = s_bp[(t - 1) * KK + tg];
                s_path[t - 1] = tg;
            }
        }
        asm volatile("bar.sync 1, 128;" ::: "memory");
#pragma unroll
        for (int i = 0; i < 2; i++) {
            int tt = tid + 128 * i;
            out_dec[(size_t)b * TT + tt] = (float)((tt < len) ? s_path[tt] : 0);
        }

    } else {
        // ============ FORWARD: 4 warps (tid 128..255), 2 threads/state ======
        const int ft = tid - 128;     // 0..127

        if (ft < 32) {
            int acc = 0;
#pragma unroll
            for (int i = 0; i < 8; i++) acc += masks[b * TT + ft + 32 * i];
#pragma unroll
            for (int o = 16; o; o >>= 1) acc += __shfl_xor_sync(0xFFFFFFFFu, acc, o);
            if (ft == 0) s_len_f = acc;
        }

        const int j = ft >> 1;       // state 0..63
        const int h = ft & 1;        // half 0..1
        const int k0 = h * 32;

        u64t E2[16];                 // exp(trans) for k0..k0+31, packed pairs
#pragma unroll
        for (int m = 0; m < 16; m++) {
            float t0 = trans_g[(k0 + 2 * m) * KK + j];
            float t1 = trans_g[(k0 + 2 * m + 1) * KK + j];
            E2[m] = pack2(expf(t0), expf(t1));
        }

        float e0 = emisb[j];
        float ecur[4];
#pragma unroll
        for (int i = 0; i < 4; i++) ecur[i] = emisb[(size_t)(1 + i) * KK + j];

        float prevP = __expf(e0);
        int iexp = 0;
        if (h == 0) s_P[0][j] = prevP;
        asm volatile("bar.sync 2, 128;" ::: "memory");
        const int len = s_len_f;
        int buf = 0;

        for (int tb = 1; tb < TT; tb += 4) {
            float enext[4];
#pragma unroll
            for (int i = 0; i < 4; i++) {
                int tt = tb + 4 + i;
                enext[i] = (tt < TT) ? emisb[(size_t)tt * KK + j] : 0.f;
            }
            float eexp[4];
#pragma unroll
            for (int i = 0; i < 4; i++) eexp[i] = __expf(ecur[i]);

#pragma unroll
            for (int i = 0; i < 4; i++) {
                const int t = tb + i;
                if (t >= TT) break;   // uniform

                float p0 = s_P[buf][0];
                const u64t* P2 = (const u64t*)&s_P[buf][k0];
                u64t s0 = 0ull, s1 = 0ull, s2 = 0ull, s3 = 0ull;
#pragma unroll
                for (int m = 0; m < 4; m++) {
                    s0 = ffma2(P2[4 * m + 0], E2[4 * m + 0], s0);
                    s1 = ffma2(P2[4 * m + 1], E2[4 * m + 1], s1);
                    s2 = ffma2(P2[4 * m + 2], E2[4 * m + 2], s2);
                    s3 = ffma2(P2[4 * m + 3], E2[4 * m + 3], s3);
                }
                float l0, h0, l1, h1, l2, h2, l3, h3;
                unpack2(s0, &l0, &h0);
                unpack2(s1, &l1, &h1);
                unpack2(s2, &l2, &h2);
                unpack2(s3, &l3, &h3);
                float S = ((l0 + h0) + (l1 + h1)) + ((l2 + h2) + (l3 + h3));
                S += __shfl_xor_sync(0xFFFFFFFFu, S, 1);   // combine halves

                int e0i = (int)(__float_as_uint(p0) >> 23);
                float scale = __uint_as_float((unsigned)(254 - e0i) << 23);
                if (t < len) {
                    prevP = S * scale * eexp[i];
                    iexp += e0i - 127;
                }
                if (h == 0) s_P[buf ^ 1][j] = prevP;
                asm volatile("bar.sync 2, 128;" ::: "memory");
                buf ^= 1;
            }
#pragma unroll
            for (int i = 0; i < 4; i++) ecur[i] = enext[i];
        }

        // log_norm: sum final P (h==0 contributions only)
        float sp = (h == 0) ? prevP : 0.f;
#pragma unroll
        for (int o = 16; o; o >>= 1) sp += __shfl_xor_sync(0xFFFFFFFFu, sp, o);
        if ((ft & 31) == 0) s_red[ft >> 5] = sp;

        // seq_score partials: 2 t's per thread
        float uacc = 0.f;
#pragma unroll
        for (int i = 0; i < 2; i++) {
            int tt = ft + 128 * i;
            if (tt < len) {
                int tg = target[b * TT + tt];
                uacc += emisb[(size_t)tt * KK + tg];
                if (tt >= 1) uacc += trans_g[target[b * TT + tt - 1] * KK + tg];
            }
        }
#pragma unroll
        for (int o = 16; o; o >>= 1) uacc += __shfl_xor_sync(0xFFFFFFFFu, uacc, o);
        if ((ft & 31) == 0) s_red[4 + (ft >> 5)] = uacc;
        asm volatile("bar.sync 2, 128;" ::: "memory");

        if (ft == 0) {
            float sumP = s_red[0] + s_red[1] + s_red[2] + s_red[3];
            float score = s_red[4] + s_red[5] + s_red[6] + s_red[7];
            const float LN2 = 0.69314718055994531f;
            out_ll[b] = score - ((float)iexp * LN2 + logf(sumP));
        }
    }
}

// ---------------------------------------------------------------------------
extern "C" void kernel_launch(void* const* d_in, const int* in_sizes, int n_in,
                              void* d_out, int out_size) {
    const float* hidden = (const float*)d_in[0];
    const int*   masks  = (const int*)d_in[1];
    const int*   target = (const int*)d_in[2];
    const float* Wm     = (const float*)d_in[3];
    const float* bias   = (const float*)d_in[4];
    const float* trans  = (const float*)d_in[5];
    float* out = (float*)d_out;

    gemm_emis_kernel<<<BB * TT / 128, 256>>>(hidden, Wm, bias);
    crf_kernel<<<BB, 256>>>(masks, target, trans, out, out + (size_t)BB * TT);
}